// round 16
// baseline (speedup 1.0000x reference)
#include <cuda_runtime.h>
#include <cuda_bf16.h>
#include <cstdint>

// FAPE loss, single fused HMMA kernel. B=4, N=2048.
// s2(i,j) = ||A_i u_j + dt_i||^2 + eps = W_i . V_j (28-dim, padded to 32)
// R16: 256x256 tiles (grid 256). Every thread builds one W row AND one V
// row; each warp owns TWO 16-row A-fragment sets so 4 B-frag LDS feed 4
// HMMAs. Epilogue pipelined against next MMAs (R15). Amortizes per-tile
// overhead 4x; total issued instrs ~halved.

#define BB 4
#define NN 2048
#define THREADS 256
#define NWARP 8
#define ITILE 256
#define JQ 256
#define NBLOCKS (BB * (NN/ITILE) * (NN/JQ))   // 4*8*8 = 256
#define SROW 20     // u32 stride of V rows in smem (B-frag reads conflict-free)
#define WROW 17     // u32 stride of W rows in smem
#define PPB  ((NN/ITILE) * (NN/JQ))           // partials per batch = 64

__device__ float g_partials[NBLOCKS];
__device__ unsigned int g_count = 0;

__device__ __forceinline__ float fsqrt_approx(float x) {
    float y; asm("sqrt.approx.f32 %0, %1;" : "=f"(y) : "f"(x)); return y;
}
__device__ __forceinline__ void mma16816(float d[4], const uint32_t a[4],
                                         uint32_t b0, uint32_t b1,
                                         float c0, float c1, float c2, float c3) {
    asm volatile(
        "mma.sync.aligned.m16n8k16.row.col.f32.bf16.bf16.f32 "
        "{%0,%1,%2,%3}, {%4,%5,%6,%7}, {%8,%9}, {%10,%11,%12,%13};"
        : "=f"(d[0]), "=f"(d[1]), "=f"(d[2]), "=f"(d[3])
        : "r"(a[0]), "r"(a[1]), "r"(a[2]), "r"(a[3]), "r"(b0), "r"(b1),
          "f"(c0), "f"(c1), "f"(c2), "f"(c3));
}
__device__ __forceinline__ uint32_t pack_bf2(float lo, float hi) {
    __nv_bfloat162 h = __floats2bfloat162_rn(lo, hi);
    return *(uint32_t*)&h;
}

__global__ void __launch_bounds__(THREADS)
fape_fused(const float* __restrict__ pR, const float* __restrict__ pT,
           const float* __restrict__ pX, const float* __restrict__ tR,
           const float* __restrict__ tT, const float* __restrict__ tX,
           float* __restrict__ out) {
    __shared__ uint32_t sw[ITILE * WROW];     // 17 KB
    __shared__ uint32_t sv[JQ * SROW];        // 20 KB
    __shared__ float swred[NWARP];
    __shared__ int s_last;

    const int bid = blockIdx.x;
    const int b  = bid >> 6;
    const int it = (bid >> 3) & 7;
    const int jq = bid & 7;
    const int t  = threadIdx.x;
    const int w  = t >> 5;
    const int lane = t & 31;
    const int gr = lane >> 2;
    const int tg = lane & 3;

    // ---- Build: every thread builds W row t AND V row t (direct from gmem) ----
    {
        const int i = b * NN + it * ITILE + t;
        float Rp[9], Rt[9];
#pragma unroll
        for (int k = 0; k < 9; k++) Rp[k] = pR[i * 9 + k];
#pragma unroll
        for (int k = 0; k < 9; k++) Rt[k] = tR[i * 9 + k];
        const float tp0 = pT[i*3+0], tp1 = pT[i*3+1], tp2 = pT[i*3+2];
        const float tt0 = tT[i*3+0], tt1 = tT[i*3+1], tt2 = tT[i*3+2];
        float A[3][6], dt[3], v[28];
#pragma unroll
        for (int r = 0; r < 3; r++) {
#pragma unroll
            for (int k = 0; k < 3; k++) {
                A[r][k]     =  Rp[k*3 + r];
                A[r][k + 3] = -Rt[k*3 + r];
            }
            dt[r] = (Rt[0*3+r]*tt0 + Rt[1*3+r]*tt1 + Rt[2*3+r]*tt2)
                  - (Rp[0*3+r]*tp0 + Rp[1*3+r]*tp1 + Rp[2*3+r]*tp2);
        }
#pragma unroll
        for (int k = 0; k < 6; k++)
            v[k] = A[0][k]*A[0][k] + A[1][k]*A[1][k] + A[2][k]*A[2][k];
        int p = 6;
#pragma unroll
        for (int k = 0; k < 6; k++)
#pragma unroll
            for (int l = k + 1; l < 6; l++)
                v[p++] = 2.0f * (A[0][k]*A[0][l] + A[1][k]*A[1][l] + A[2][k]*A[2][l]);
#pragma unroll
        for (int k = 0; k < 6; k++)
            v[21 + k] = 2.0f * (A[0][k]*dt[0] + A[1][k]*dt[1] + A[2][k]*dt[2]);
        v[27] = dt[0]*dt[0] + dt[1]*dt[1] + dt[2]*dt[2] + 1e-4f;

        uint32_t* dst = sw + t * WROW;
#pragma unroll
        for (int c = 0; c < 14; c++) dst[c] = pack_bf2(v[2*c], v[2*c+1]);
        dst[14] = 0u; dst[15] = 0u;
    }
    {
        const int j = b * NN + jq * JQ + t;
        const float xp0 = pX[j*3+0], xp1 = pX[j*3+1], xp2 = pX[j*3+2];
        const float xt0 = tX[j*3+0], xt1 = tX[j*3+1], xt2 = tX[j*3+2];
        float u[6] = {xp0, xp1, xp2, xt0, xt1, xt2};
        float v[28];
#pragma unroll
        for (int k = 0; k < 6; k++) v[k] = u[k] * u[k];
        int p = 6;
#pragma unroll
        for (int k = 0; k < 6; k++)
#pragma unroll
            for (int l = k + 1; l < 6; l++) v[p++] = u[k] * u[l];
#pragma unroll
        for (int k = 0; k < 6; k++) v[21 + k] = u[k];
        v[27] = 1.0f;
        uint32_t* dst = sv + t * SROW;
#pragma unroll
        for (int c = 0; c < 14; c++) dst[c] = pack_bf2(v[2*c], v[2*c+1]);
        dst[14] = 0u; dst[15] = 0u;
    }
    __syncthreads();

    // ---- Two A-fragment sets per warp: tile0 rows w*16.., tile1 rows 128+w*16.. ----
    uint32_t A0a[4], A1a[4], A0b[4], A1b[4];
    {
        const uint32_t* r0 = sw + (w * 16 + gr) * WROW;
        const uint32_t* r8 = sw + (w * 16 + gr + 8) * WROW;
        A0a[0] = r0[tg];      A0a[1] = r8[tg];
        A0a[2] = r0[tg + 4];  A0a[3] = r8[tg + 4];
        A1a[0] = r0[tg + 8];  A1a[1] = r8[tg + 8];
        A1a[2] = r0[tg + 12]; A1a[3] = r8[tg + 12];
        const uint32_t* s0 = sw + (128 + w * 16 + gr) * WROW;
        const uint32_t* s8 = sw + (128 + w * 16 + gr + 8) * WROW;
        A0b[0] = s0[tg];      A0b[1] = s8[tg];
        A0b[2] = s0[tg + 4];  A0b[3] = s8[tg + 4];
        A1b[0] = s0[tg + 8];  A1b[1] = s8[tg + 8];
        A1b[2] = s0[tg + 12]; A1b[3] = s8[tg + 12];
    }

    // ---- Pipelined MMA sweep over 256 j's (8 per step, 2 i-tiles) ----
    float acc0 = 0.f, acc1 = 0.f;
    const uint32_t* vr = sv + gr * SROW + tg;

    float dA0[4], dA1[4];
    {   // prologue
        const uint32_t b0 = vr[0], b1 = vr[4], b2 = vr[8], b3 = vr[12];
        vr += 8 * SROW;
        mma16816(dA0, A0a, b0, b1, 0.f, 0.f, 0.f, 0.f);
        mma16816(dA0, A1a, b2, b3, dA0[0], dA0[1], dA0[2], dA0[3]);
        mma16816(dA1, A0b, b0, b1, 0.f, 0.f, 0.f, 0.f);
        mma16816(dA1, A1b, b2, b3, dA1[0], dA1[1], dA1[2], dA1[3]);
    }
#pragma unroll
    for (int j0 = 8; j0 < JQ; j0 += 8) {
        const uint32_t b0 = vr[0], b1 = vr[4], b2 = vr[8], b3 = vr[12];
        vr += 8 * SROW;
        float dB0[4], dB1[4];
        mma16816(dB0, A0a, b0, b1, 0.f, 0.f, 0.f, 0.f);
        mma16816(dB0, A1a, b2, b3, dB0[0], dB0[1], dB0[2], dB0[3]);
        mma16816(dB1, A0b, b0, b1, 0.f, 0.f, 0.f, 0.f);
        mma16816(dB1, A1b, b2, b3, dB1[0], dB1[1], dB1[2], dB1[3]);

        // epilogue of previous stage (8 pairs), overlapped with in-flight MMAs
#pragma unroll
        for (int e = 0; e < 4; e++) {
            acc0 += fsqrt_approx(fminf(fabsf(dA0[e]), 100.0f));
            acc1 += fsqrt_approx(fminf(fabsf(dA1[e]), 100.0f));
        }
#pragma unroll
        for (int e = 0; e < 4; e++) { dA0[e] = dB0[e]; dA1[e] = dB1[e]; }
    }
    // drain
#pragma unroll
    for (int e = 0; e < 4; e++) {
        acc0 += fsqrt_approx(fminf(fabsf(dA0[e]), 100.0f));
        acc1 += fsqrt_approx(fminf(fabsf(dA1[e]), 100.0f));
    }

    // ---- Deterministic reduction + last-block finalize ----
    float acc = acc0 + acc1;
#pragma unroll
    for (int m = 16; m >= 1; m >>= 1)
        acc += __shfl_xor_sync(0xffffffffu, acc, m);
    if (lane == 0) swred[w] = acc;
    __syncthreads();
    if (t == 0) {
        float part = 0.f;
#pragma unroll
        for (int q = 0; q < NWARP; q++) part += swred[q];
        g_partials[bid] = part;
        __threadfence();
        const unsigned r = atomicAdd(&g_count, 1);
        s_last = (r == NBLOCKS - 1);
    }
    __syncthreads();

    if (s_last && w < BB) {
        // warp w finalizes batch w: 64 partials, fixed order per lane.
        float s = 0.f;
#pragma unroll
        for (int q = lane; q < PPB; q += 32)
            s += __ldcg(&g_partials[w * PPB + q]);
#pragma unroll
        for (int m = 16; m >= 1; m >>= 1)
            s += __shfl_xor_sync(0xffffffffu, s, m);
        if (lane == 0)
            out[w] = s * (1.0f / (10.0f * (float)NN * (float)NN));
        if (t == 0) g_count = 0;   // reset for graph replay
    }
}

extern "C" void kernel_launch(void* const* d_in, const int* in_sizes, int n_in,
                              void* d_out, int out_size) {
    const float* pR = (const float*)d_in[0];  // predicted_rotations   [B,N,3,3]
    const float* pT = (const float*)d_in[1];  // predicted_translations[B,N,3]
    const float* pX = (const float*)d_in[2];  // predicted_atom_positions
    const float* tR = (const float*)d_in[3];  // true_rotations
    const float* tT = (const float*)d_in[4];  // true_translations
    const float* tX = (const float*)d_in[5];  // true_atom_positions

    fape_fused<<<NBLOCKS, THREADS>>>(pR, pT, pX, tR, tT, tX, (float*)d_out);
}